// round 9
// baseline (speedup 1.0000x reference)
#include <cuda_runtime.h>
#include <cuda_bf16.h>

// ApproxEMD: B=16, N=2048, D=3. Flash-style, fused, spatially sorted.
// Init: bitonic-sort preds & labels of each batch by x-coordinate; all state
// (curr/cost/partials) lives in permuted space (final output is a scalar ->
// permutation invariant). Sorted order gives every row-chunk and every warp's
// 128 contiguous columns a tight x-interval, so d(n,m) >= gap(x)^2 gives a
// warp x chunk level bound: if efl*gap^2 < -150, exp2 of every pair in the
// 128x128 tile is exactly +0.0f -> skip the whole loop with ONE uniform branch.
// Per step: colpass (fused currency update) + rowpass (fused g/cost update).
// f32x2 packed math, 4 outputs/thread, MUFU.EX2 as designed bottleneck.

#define BB 16
#define NN 2048
#define BN (BB*NN)
#define EPSV 1e-9f
#define CH 128            // rows/cols per smem chunk
#define NCHUNK (NN/CH)    // 16
#define TPB 128
#define UTH (-150.0f)     // exp2(arg)==+0.0f for arg < -150

// permuted (x-sorted) copies, SoA
__device__ float g_spx[BN], g_spy[BN], g_spz[BN], g_spn[BN];   // preds
__device__ float g_slx[BN], g_sly[BN], g_slz[BN], g_slm[BN];   // labels
__device__ float g_curr2[2][BN];
__device__ float g_cost2[2][BN];
__device__ float g_SEp[NCHUNK][BN];
__device__ float g_SECp[NCHUNK][BN];
__device__ float g_Rp[NCHUNK][BN];
__device__ double g_out;

typedef unsigned long long u64;

__device__ __forceinline__ float ex2f(float x) {
    float r;
    asm("ex2.approx.f32 %0, %1;" : "=f"(r) : "f"(x));
    return r;
}
__device__ __forceinline__ u64 pk(float lo, float hi) {
    u64 d;
    asm("mov.b64 %0, {%1, %2};" : "=l"(d)
        : "r"(__float_as_uint(lo)), "r"(__float_as_uint(hi)));
    return d;
}
__device__ __forceinline__ void upk(u64 v, float& lo, float& hi) {
    unsigned a, b;
    asm("mov.b64 {%0, %1}, %2;" : "=r"(a), "=r"(b) : "l"(v));
    lo = __uint_as_float(a); hi = __uint_as_float(b);
}
__device__ __forceinline__ u64 fma2(u64 a, u64 b, u64 c) {
    u64 d;
    asm("fma.rn.f32x2 %0, %1, %2, %3;" : "=l"(d) : "l"(a), "l"(b), "l"(c));
    return d;
}
__device__ __forceinline__ u64 add2(u64 a, u64 b) {
    u64 d;
    asm("add.rn.f32x2 %0, %1, %2;" : "=l"(d) : "l"(a), "l"(b));
    return d;
}
__device__ __forceinline__ u64 mul2(u64 a, u64 b) {
    u64 d;
    asm("mul.rn.f32x2 %0, %1, %2;" : "=l"(d) : "l"(a), "l"(b));
    return d;
}

// Sort one (side, batch): bitonic sort of 2048 (x-key, idx) pairs in smem,
// then gather into permuted SoA arrays + init state. grid (2, BB), block 1024.
__global__ void __launch_bounds__(1024) k_sort(
    const float* __restrict__ preds, const float* __restrict__ labels) {
    const int side = blockIdx.x;       // 0 = preds, 1 = labels
    const int b = blockIdx.y;
    const float* src = side ? labels : preds;
    __shared__ u64 s[NN];
    const int tid = threadIdx.x;

    for (int i = tid; i < NN; i += 1024) {
        float x = src[((size_t)b * NN + i) * 3];
        unsigned u = __float_as_uint(x);
        u = (u & 0x80000000u) ? ~u : (u | 0x80000000u);  // orderable transform
        s[i] = ((u64)u << 32) | (unsigned)i;
    }
    for (int k = 2; k <= NN; k <<= 1) {
        for (int j = k >> 1; j > 0; j >>= 1) {
            __syncthreads();
            for (int i = tid; i < NN; i += 1024) {
                int ixj = i ^ j;
                if (ixj > i) {
                    bool up = ((i & k) == 0);
                    u64 a = s[i], c = s[ixj];
                    if ((a > c) == up) { s[i] = c; s[ixj] = a; }
                }
            }
        }
    }
    __syncthreads();
    for (int i = tid; i < NN; i += 1024) {
        int idx = (int)(s[i] & 0xFFFFFFFFu);
        const float* q = src + ((size_t)b * NN + idx) * 3;
        float x = q[0], y = q[1], z = q[2];
        int o = b * NN + i;
        if (side) {
            g_slx[o] = x; g_sly[o] = y; g_slz[o] = z;
            g_slm[o] = x*x + y*y + z*z;
            g_cost2[0][o] = 1.0f;
        } else {
            g_spx[o] = x; g_spy[o] = y; g_spz[o] = z;
            g_spn[o] = x*x + y*y + z*z;
            g_curr2[0][o] = 1.0f;
#pragma unroll
            for (int ch = 0; ch < NCHUNK; ch++) g_Rp[ch][o] = 0.0f;
        }
    }
    if (side == 0 && b == 0 && tid == 0) g_out = 0.0;
}

// colpass: fused currency update + column sums + warp-x-chunk skip.
// grid (NCHUNK, 4, BB), block 128. Warp owns 128 contiguous sorted columns;
// thread owns 4 (lane, +32, +64, +96).
__global__ void __launch_bounds__(TPB) k_colpass(float efl, int par) {
    const int b = blockIdx.z;
    const int chunk = blockIdx.x;
    __shared__ ulonglong2 sA[CH];  // (px2, py2) broadcast-packed
    __shared__ ulonglong2 sB[CH];  // (pz2, wn2) wn = efl*|p|^2
    __shared__ u64        sC[CH];  // (c, c)

    {
        const int n = b * NN + chunk * CH + threadIdx.x;
        float r = 0.0f;
#pragma unroll
        for (int ch = 0; ch < NCHUNK; ch++) r += g_Rp[ch][n];
        float cu = g_curr2[par][n];
        float c = fmaxf(cu - cu * r, 0.0f);
        g_curr2[1 - par][n] = c;     // duplicate identical write across y-blocks
        float wn = efl * g_spn[n];
        sA[threadIdx.x] = make_ulonglong2(pk(g_spx[n], g_spx[n]), pk(g_spy[n], g_spy[n]));
        sB[threadIdx.x] = make_ulonglong2(pk(g_spz[n], g_spz[n]), pk(wn, wn));
        sC[threadIdx.x] = pk(c, c);
    }
    __syncthreads();

    const int lane = threadIdx.x & 31;
    const int w = threadIdx.x >> 5;
    const int wb = b * NN + blockIdx.y * 512 + w * 128;   // warp column base
    const int m0 = wb + lane;

    // warp x chunk separation bound (both sides x-sorted)
    const int rb = b * NN + chunk * CH;
    float rlo = g_spx[rb], rhi = g_spx[rb + CH - 1];
    float clo = g_slx[wb], chi = g_slx[wb + 127];
    float gap = fmaxf(0.0f, fmaxf(rlo - chi, clo - rhi));
    bool alive = (efl * gap * gap) >= UTH;   // else every pair's E == +0.0f

    float e0 = 0, e1 = 0, e2 = 0, e3 = 0, c0 = 0, c1 = 0, c2v = 0, c3 = 0;
    if (alive) {
        const float m2 = -2.0f * efl;
        const u64 lxA = pk(m2 * g_slx[m0], m2 * g_slx[m0 + 32]);
        const u64 lyA = pk(m2 * g_sly[m0], m2 * g_sly[m0 + 32]);
        const u64 lzA = pk(m2 * g_slz[m0], m2 * g_slz[m0 + 32]);
        const u64 lxB = pk(m2 * g_slx[m0 + 64], m2 * g_slx[m0 + 96]);
        const u64 lyB = pk(m2 * g_sly[m0 + 64], m2 * g_sly[m0 + 96]);
        const u64 lzB = pk(m2 * g_slz[m0 + 64], m2 * g_slz[m0 + 96]);
        const u64 wbA = pk(efl * g_slm[m0],      efl * g_slm[m0 + 32]);
        const u64 wbB = pk(efl * g_slm[m0 + 64], efl * g_slm[m0 + 96]);

        u64 sEA = 0ull, sECA = 0ull, sEB = 0ull, sECB = 0ull;
#pragma unroll 8
        for (int i = 0; i < CH; i++) {
            ulonglong2 A = sA[i];
            ulonglong2 Bv = sB[i];
            u64 cc = sC[i];
            u64 argA = fma2(Bv.x, lzA, fma2(A.y, lyA, fma2(A.x, lxA, add2(Bv.y, wbA))));
            u64 argB = fma2(Bv.x, lzB, fma2(A.y, lyB, fma2(A.x, lxB, add2(Bv.y, wbB))));
            float a0, a1, b0, b1;
            upk(argA, a0, a1); upk(argB, b0, b1);
            u64 eA = pk(ex2f(a0), ex2f(a1));
            u64 eB = pk(ex2f(b0), ex2f(b1));
            sEA = add2(sEA, eA); sECA = fma2(eA, cc, sECA);
            sEB = add2(sEB, eB); sECB = fma2(eB, cc, sECB);
        }
        upk(sEA, e0, e1); upk(sEB, e2, e3);
        upk(sECA, c0, c1); upk(sECB, c2v, c3);
    }
    g_SEp [chunk][m0     ] = e0;
    g_SEp [chunk][m0 + 32] = e1;
    g_SEp [chunk][m0 + 64] = e2;
    g_SEp [chunk][m0 + 96] = e3;
    g_SECp[chunk][m0     ] = c0;
    g_SECp[chunk][m0 + 32] = c1;
    g_SECp[chunk][m0 + 64] = c2v;
    g_SECp[chunk][m0 + 96] = c3;
}

// rowpass: fused g/cost update + row sums + output accumulation + skip.
// grid (NCHUNK, 4, BB), block 128.
__global__ void __launch_bounds__(TPB) k_rowpass(float efl, float inv_efl, int par) {
    const int b = blockIdx.z;
    const int chunk = blockIdx.x;
    __shared__ ulonglong2 sA[CH];  // (lx2, ly2) broadcast-packed
    __shared__ ulonglong2 sB[CH];  // (lz2, wl2) wl = efl*|l|^2
    __shared__ u64        sG[CH];  // (g, g)
    __shared__ float      sred[4];

    {
        const int m = b * NN + chunk * CH + threadIdx.x;
        float se = 0.0f, sec = 0.0f;
#pragma unroll
        for (int ch = 0; ch < NCHUNK; ch++) {
            se += g_SEp[ch][m];
            sec += g_SECp[ch][m];
        }
        float cost = g_cost2[par][m];
        float s1 = cost * se;
        float s2 = cost * sec / (s1 + EPSV);
        float wt = fminf(cost / (s2 + EPSV), 1.0f);
        float gv = cost * wt / (s1 + EPSV);
        g_cost2[1 - par][m] = fmaxf(cost - s2 * wt, 0.0f);  // dup identical write
        float wl = efl * g_slm[m];
        sA[threadIdx.x] = make_ulonglong2(pk(g_slx[m], g_slx[m]), pk(g_sly[m], g_sly[m]));
        sB[threadIdx.x] = make_ulonglong2(pk(g_slz[m], g_slz[m]), pk(wl, wl));
        sG[threadIdx.x] = pk(gv, gv);
    }
    __syncthreads();

    const int lane = threadIdx.x & 31;
    const int w = threadIdx.x >> 5;
    const int wbv = b * NN + blockIdx.y * 512 + w * 128;  // warp row base
    const int n0 = wbv + lane;

    const int cb = b * NN + chunk * CH;
    float clo = g_slx[cb], chi = g_slx[cb + CH - 1];
    float rlo = g_spx[wbv], rhi = g_spx[wbv + 127];
    float gap = fmaxf(0.0f, fmaxf(rlo - chi, clo - rhi));
    bool alive = (efl * gap * gap) >= UTH;

    float r0 = 0, r1 = 0, r2 = 0, r3 = 0;
    float v = 0.0f;
    if (alive) {
        const float m2 = -2.0f * efl;
        const u64 pxA = pk(m2 * g_spx[n0], m2 * g_spx[n0 + 32]);
        const u64 pyA = pk(m2 * g_spy[n0], m2 * g_spy[n0 + 32]);
        const u64 pzA = pk(m2 * g_spz[n0], m2 * g_spz[n0 + 32]);
        const u64 pxB = pk(m2 * g_spx[n0 + 64], m2 * g_spx[n0 + 96]);
        const u64 pyB = pk(m2 * g_spy[n0 + 64], m2 * g_spy[n0 + 96]);
        const u64 pzB = pk(m2 * g_spz[n0 + 64], m2 * g_spz[n0 + 96]);
        const u64 wpA = pk(efl * g_spn[n0],      efl * g_spn[n0 + 32]);
        const u64 wpB = pk(efl * g_spn[n0 + 64], efl * g_spn[n0 + 96]);

        u64 rA = 0ull, oA = 0ull, rB = 0ull, oB = 0ull;
#pragma unroll 8
        for (int i = 0; i < CH; i++) {
            ulonglong2 A = sA[i];
            ulonglong2 Bv = sB[i];
            u64 g2 = sG[i];
            u64 argA = fma2(Bv.x, pzA, fma2(A.y, pyA, fma2(A.x, pxA, add2(Bv.y, wpA))));
            u64 argB = fma2(Bv.x, pzB, fma2(A.y, pyB, fma2(A.x, pxB, add2(Bv.y, wpB))));
            float a0, a1, b0, b1;
            upk(argA, a0, a1); upk(argB, b0, b1);
            u64 eA = pk(ex2f(a0), ex2f(a1));
            u64 eB = pk(ex2f(b0), ex2f(b1));
            u64 tA = mul2(eA, g2);
            u64 tB = mul2(eB, g2);
            rA = add2(rA, tA); oA = fma2(tA, argA, oA);   // o accumulates efl*t*d
            rB = add2(rB, tB); oB = fma2(tB, argB, oB);
        }
        float o0, o1, o2, o3;
        upk(rA, r0, r1); upk(rB, r2, r3);
        upk(oA, o0, o1); upk(oB, o2, o3);
        const float* cu = g_curr2[1 - par];
        v = inv_efl * (cu[n0] * o0 + cu[n0 + 32] * o1 +
                       cu[n0 + 64] * o2 + cu[n0 + 96] * o3);
    }
    g_Rp[chunk][n0     ] = r0;
    g_Rp[chunk][n0 + 32] = r1;
    g_Rp[chunk][n0 + 64] = r2;
    g_Rp[chunk][n0 + 96] = r3;

#pragma unroll
    for (int off = 16; off > 0; off >>= 1)
        v += __shfl_down_sync(0xFFFFFFFFu, v, off);
    if (lane == 0) sred[w] = v;
    __syncthreads();
    if (threadIdx.x == 0) {
        float s = sred[0] + sred[1] + sred[2] + sred[3];
        atomicAdd(&g_out, (double)s);
    }
}

// Last step (ef==0): E==1 everywhere -> closed form O(N) per batch.
__global__ void k_ef0() {
    const int b = blockIdx.x;
    const int tid = threadIdx.x;
    __shared__ float red[256];

    float C = 0, CP = 0, CX = 0, CY = 0, CZ = 0;
    for (int n = tid; n < NN; n += 256) {
        int idx = b * NN + n;
        float r = 0.0f;
#pragma unroll
        for (int ch = 0; ch < NCHUNK; ch++) r += g_Rp[ch][idx];
        float cu = g_curr2[1][idx];
        float c = fmaxf(cu - cu * r, 0.0f);
        C += c; CP += c * g_spn[idx];
        CX += c * g_spx[idx]; CY += c * g_spy[idx]; CZ += c * g_spz[idx];
    }
    auto reduce = [&](float v) -> float {
        red[tid] = v; __syncthreads();
        for (int s = 128; s > 0; s >>= 1) {
            if (tid < s) red[tid] += red[tid + s];
            __syncthreads();
        }
        float r = red[0]; __syncthreads();
        return r;
    };
    float Cs = reduce(C);
    float CPs = reduce(CP);
    float CXs = reduce(CX);
    float CYs = reduce(CY);
    float CZs = reduce(CZ);

    float G = 0, GL = 0, GX = 0, GY = 0, GZ = 0;
    for (int m = tid; m < NN; m += 256) {
        int idx = b * NN + m;
        float cost = g_cost2[1][idx];   // cost after step 8
        float s1 = cost * (float)NN;
        float s2 = cost * Cs / (s1 + EPSV);
        float wt = fminf(cost / (s2 + EPSV), 1.0f);
        float g = cost * wt / (s1 + EPSV);
        G += g; GL += g * g_slm[idx];
        GX += g * g_slx[idx]; GY += g * g_sly[idx]; GZ += g * g_slz[idx];
    }
    float Gs = reduce(G);
    float GLs = reduce(GL);
    float GXs = reduce(GX);
    float GYs = reduce(GY);
    float GZs = reduce(GZ);

    if (tid == 0) {
        double ob = (double)CPs * Gs + (double)Cs * GLs
                  - 2.0 * ((double)CXs * GXs + (double)CYs * GYs + (double)CZs * GZs);
        atomicAdd(&g_out, ob);
    }
}

__global__ void k_write(float* out) {
    out[0] = (float)g_out;
}

extern "C" void kernel_launch(void* const* d_in, const int* in_sizes, int n_in,
                              void* d_out, int out_size) {
    const float* preds = (const float*)d_in[0];
    const float* labels = (const float*)d_in[1];
    float* out = (float*)d_out;

    static const float EF[9] = {
        -16384.0f, -4096.0f, -1024.0f, -256.0f, -64.0f,
        -16.0f, -4.0f, -1.0f, -0.25f
    };
    const float L2E = 1.4426950408889634f;

    k_sort<<<dim3(2, BB), 1024>>>(preds, labels);

    dim3 grid(NCHUNK, 4, BB);   // 1024 blocks of 128 threads
    for (int s = 0; s < 9; s++) {
        float efl = EF[s] * L2E;
        int par = s & 1;
        k_colpass<<<grid, TPB>>>(efl, par);
        k_rowpass<<<grid, TPB>>>(efl, 1.0f / efl, par);
    }
    k_ef0<<<BB, 256>>>();   // ef = 0 step, closed form
    k_write<<<1, 1>>>(out);
}